// round 13
// baseline (speedup 1.0000x reference)
#include <cuda_runtime.h>
#include <cuda_fp16.h>
#include <cstdint>
#include <math.h>

#define BB  4
#define LL  1024
#define DD  1024
#define HH  16
#define DHH 64
#define FF  7
#define BLD (BB*LL*DD)

// ---- scratch (module-static device memory; no runtime allocation) ----
__device__ __align__(16) __half g_SH[(size_t)BB*HH*LL*LL];    // raw scores fp16
__device__ __align__(16) __half g_attnH[(size_t)BB*HH*LL*LL]; // attn fp16 copy
__device__ __align__(16) __half g_xH[3*BLD];      // fp16 q,k,v inputs; later Vt
__device__ __align__(16) __half g_WH[3*DD*DD];    // fp16 W_q,W_k,W_v
__device__ __align__(16) __half g_QKVH[3*BLD];    // projected Q,K,V fp16
__device__ __align__(16) __half g_AOH[BLD];
__device__ __align__(16) __half g_WoH[DD*DD];

// ============================================================================
// helpers
// ============================================================================
__device__ __forceinline__ uint32_t smem_u32(const void* p) {
    uint32_t a;
    asm("{ .reg .u64 t; cvta.to.shared.u64 t, %1; cvt.u32.u64 %0, t; }" : "=r"(a) : "l"(p));
    return a;
}
__device__ __forceinline__ void cp16(uint32_t s, const void* g) {
    asm volatile("cp.async.cg.shared.global [%0], [%1], 16;" :: "r"(s), "l"(g) : "memory");
}
#define CP_COMMIT() asm volatile("cp.async.commit_group;" ::: "memory")
#define CP_WAIT1()  asm volatile("cp.async.wait_group 1;" ::: "memory")

#define LDSM4(r0, r1, r2, r3, addr) \
    asm volatile("ldmatrix.sync.aligned.m8n8.x4.shared.b16 {%0,%1,%2,%3}, [%4];" \
        : "=r"(r0), "=r"(r1), "=r"(r2), "=r"(r3) : "r"(addr))

#define MMA_F16(c, a, b) \
    asm volatile("mma.sync.aligned.m16n8k16.row.col.f32.f16.f16.f32 " \
        "{%0,%1,%2,%3}, {%4,%5,%6,%7}, {%8,%9}, {%0,%1,%2,%3};" \
        : "+f"((c)[0]), "+f"((c)[1]), "+f"((c)[2]), "+f"((c)[3]) \
        : "r"((a)[0]), "r"((a)[1]), "r"((a)[2]), "r"((a)[3]), \
          "r"((b)[0]), "r"((b)[1]))

// ============================================================================
// fused fp32 -> fp16 conversion for 7 tensors (blockIdx.y selects tensor)
// ============================================================================
struct CvtArgs {
    const float* src[7];
    __half*      dst[7];
    int          n8[7];   // elements / 8
};

__global__ __launch_bounds__(256)
void cvt_f16(CvtArgs args)
{
    const int t = blockIdx.y;
    const float4* src = (const float4*)args.src[t];
    __half2*      dst = (__half2*)args.dst[t];
    const int n8 = args.n8[t];
    for (int i = blockIdx.x * 256 + threadIdx.x; i < n8; i += gridDim.x * 256) {
        float4 a = src[i * 2], b = src[i * 2 + 1];
        dst[i * 4 + 0] = __floats2half2_rn(a.x, a.y);
        dst[i * 4 + 1] = __floats2half2_rn(a.z, a.w);
        dst[i * 4 + 2] = __floats2half2_rn(b.x, b.y);
        dst[i * 4 + 3] = __floats2half2_rn(b.z, b.w);
    }
}

// ============================================================================
// Tensor-core fp16 GEMM (fp32 accum): C[m,n] = alpha*sum_k A[m,k]*B[n,k]
// (+bias[n] when zd==biasZ). 64x64 warp tiles; BK=64; up-to-3-stage cp.async.
// NOTE: launch with dynamic smem = min(K/64, 3) * (BM+BN) * 144 bytes.
// ============================================================================
template<int BM, int BN, bool HOUT>
__global__ void __launch_bounds__((BM/64)*(BN/64)*32)
hgemm(const __half* __restrict__ A, const __half* __restrict__ B,
      const float* __restrict__ bias, void* __restrict__ Cv,
      int K, int lda, int ldb, int ldc, int hmod,
      long long aS1, long long aS2, long long bS1, long long bS2,
      long long cS1, long long cS2, float alpha, int biasZ)
{
    constexpr int WARPS_M = BM / 64, WARPS_N = BN / 64;
    constexpr int NTHR = WARPS_M * WARPS_N * 32;
    constexpr int BK = 64;                 // halves per chunk
    constexpr int RB = 144;                // bytes per padded row
    constexpr int STB = (BM + BN) * RB;    // bytes per stage
    constexpr int A_IT = BM * 8 / NTHR;
    constexpr int B_IT = BN * 8 / NTHR;
    constexpr int RSTEP = NTHR / 8;
    constexpr int MT = 4, NT = 8;

    extern __shared__ char smc[];

    const int tid = threadIdx.x, lane = tid & 31, wid = tid >> 5;
    const int wm = wid % WARPS_M, wn = wid / WARPS_M;
    const int z = blockIdx.z, zd = z / hmod, zm = z % hmod;
    const __half* Ab = A + zd * aS1 + zm * aS2;
    const __half* Bb = B + zd * bS1 + zm * bS2;
    const int m0 = blockIdx.y * BM, n0 = blockIdx.x * BN;
    const bool useBias = (bias != nullptr) && (zd == biasZ);

    const int lrow = tid >> 3, lq = tid & 7;
    const __half* aG = Ab + (size_t)(m0 + lrow) * lda + lq * 8;
    const __half* bG = Bb + (size_t)(n0 + lrow) * ldb + lq * 8;
    const uint32_t smB = smem_u32(smc);
    const uint32_t aSo = (uint32_t)(lrow * RB + lq * 16);
    const uint32_t bSo = (uint32_t)((BM + lrow) * RB + lq * 16);

    const int mj = lane >> 3, mr = lane & 7;
    const int rowA  = wm * 64 + ((mj & 1) << 3) + mr;
    const uint32_t kByA = (uint32_t)(mj >> 1) * 16;
    const int rowB  = BM + wn * 64 + ((mj >> 1) << 3) + mr;
    const uint32_t kByB = (uint32_t)(mj & 1) * 16;

    float acc[MT][NT][4];
    #pragma unroll
    for (int i = 0; i < MT; i++)
        #pragma unroll
        for (int j = 0; j < NT; j++)
            #pragma unroll
            for (int r = 0; r < 4; r++) acc[i][j][r] = 0.f;

    const int NC = K / BK;

    auto LOAD = [&](int c, int s) {
        const uint32_t stb = smB + (uint32_t)s * STB;
        const __half* ap = aG + c * BK;
        const __half* bp = bG + c * BK;
        #pragma unroll
        for (int it = 0; it < A_IT; it++)
            cp16(stb + aSo + (uint32_t)it * RSTEP * RB,
                 ap + (size_t)it * RSTEP * lda);
        #pragma unroll
        for (int it = 0; it < B_IT; it++)
            cp16(stb + bSo + (uint32_t)it * RSTEP * RB,
                 bp + (size_t)it * RSTEP * ldb);
    };

    LOAD(0, 0); CP_COMMIT();
    if (NC > 1) LOAD(1, 1);
    CP_COMMIT();

    for (int c = 0; c < NC; c++) {
        CP_WAIT1();
        __syncthreads();
        if (c + 2 < NC) LOAD(c + 2, (c + 2) % 3);
        CP_COMMIT();

        const uint32_t stb = smB + (uint32_t)(c % 3) * STB;
        #pragma unroll
        for (int kk = 0; kk < 4; kk++) {
            uint32_t af[MT][4], bf[NT][2];
            #pragma unroll
            for (int mt = 0; mt < MT; mt++) {
                const uint32_t ad = stb + (uint32_t)(rowA + mt * 16) * RB
                                  + kk * 32 + kByA;
                LDSM4(af[mt][0], af[mt][1], af[mt][2], af[mt][3], ad);
            }
            #pragma unroll
            for (int p = 0; p < 4; p++) {
                const uint32_t bd = stb + (uint32_t)(rowB + p * 16) * RB
                                  + kk * 32 + kByB;
                LDSM4(bf[2*p][0], bf[2*p][1], bf[2*p+1][0], bf[2*p+1][1], bd);
            }
            #pragma unroll
            for (int mt = 0; mt < MT; mt++)
                #pragma unroll
                for (int nt = 0; nt < NT; nt++)
                    MMA_F16(acc[mt][nt], af[mt], bf[nt]);
        }
    }

    #pragma unroll
    for (int mt = 0; mt < MT; mt++) {
        const int m = m0 + wm * 64 + mt * 16 + (lane >> 2);
        #pragma unroll
        for (int nt = 0; nt < NT; nt++) {
            const int n = n0 + wn * 64 + nt * 8 + 2 * (lane & 3);
            float bx = 0.f, by = 0.f;
            if (useBias) { bx = bias[n]; by = bias[n + 1]; }
            float2 v0 = { acc[mt][nt][0] * alpha + bx, acc[mt][nt][1] * alpha + by };
            float2 v1 = { acc[mt][nt][2] * alpha + bx, acc[mt][nt][3] * alpha + by };
            if (HOUT) {
                __half* Cb = (__half*)Cv + zd * cS1 + zm * cS2;
                *(__half2*)(Cb + (size_t)m * ldc + n)       = __floats2half2_rn(v0.x, v0.y);
                *(__half2*)(Cb + (size_t)(m + 8) * ldc + n) = __floats2half2_rn(v1.x, v1.y);
            } else {
                float* Cb = (float*)Cv + zd * cS1 + zm * cS2;
                *(float2*)(Cb + (size_t)m * ldc + n)       = v0;
                *(float2*)(Cb + (size_t)(m + 8) * ldc + n) = v1;
            }
        }
    }
}

// ============================================================================
// per-head V transpose (fp16): Vt[(b*H+h)][n][k] = V[b][k][h*64+n]
// ============================================================================
__global__ __launch_bounds__(256)
void transposeV(const __half* __restrict__ V, __half* __restrict__ Vt)
{
    __shared__ __half t[32][34];
    const int z = blockIdx.z;
    const int b = z >> 4, h = z & 15;
    const int k0 = blockIdx.x * 32, n0 = blockIdx.y * 32;
    const int tx = threadIdx.x & 31, ty = threadIdx.x >> 5;
    #pragma unroll
    for (int i = 0; i < 4; i++)
        t[ty + 8 * i][tx] = V[((size_t)b * LL + k0 + ty + 8 * i) * DD + h * 64 + n0 + tx];
    __syncthreads();
    #pragma unroll
    for (int i = 0; i < 4; i++)
        Vt[((size_t)z * 64 + n0 + ty + 8 * i) * LL + k0 + tx] = t[tx][ty + 8 * i];
}

// ============================================================================
// Bias network + softmax v7: register features (half2), HFMA2 dual dots,
// polynomial softplus, 4-way head batching (4 S-rows in flight, ONE combined
// block reduction per quad) to cut the serial latency chain to 4 iterations.
// ============================================================================
__global__ __launch_bounds__(256)
void bias_softmax_kernel(const __half* __restrict__ S,
                         const float* __restrict__ dq,
                         const float* __restrict__ dkt,
                         const float* __restrict__ dkb,
                         const float* __restrict__ dks,
                         const float* __restrict__ relt,
                         const float* __restrict__ relb,
                         const float* __restrict__ Ww,
                         const float* __restrict__ Wb,
                         float* __restrict__ attn,
                         __half* __restrict__ attnH)
{
    __shared__ __half2 sWp[HH*FF];   // (Ww, Wb) pairs
    __shared__ float red[4][8];

    const int bi  = blockIdx.x;
    const int b   = bi >> 10;
    const int tid = threadIdx.x;
    const int lane = tid & 31, wrp = tid >> 5;
    const int j0  = tid * 4;         // this thread owns columns j0..j0+3

    if (tid < HH*FF) sWp[tid] = __floats2half2_rn(Ww[tid], Wb[tid]);

    const float dq0 = dq[bi*3+0], dq1 = dq[bi*3+1], dq2 = dq[bi*3+2];
    const size_t riBase = (size_t)bi * LL * 4;

    // ---- features for 4 consecutive columns, packed (ft,ft) half2 ----
    __half2 ftp[4][FF];
    #pragma unroll
    for (int c = 0; c < 4; c++) {
        const int j = j0 + c;
        const float* kt = dkt + ((size_t)b*LL + j)*3;
        const float* kb = dkb + ((size_t)b*LL + j)*3;
        const float* ks = dks + ((size_t)b*LL + j)*14;
        const float4 rt = *(const float4*)(relt + riBase + (size_t)j*4);
        const float4 rb = *(const float4*)(relb + riBase + (size_t)j*4);
        float top[FF] = { dq0-kt[0], dq1-kt[1], dq2-kt[2], rt.x, rt.y, rt.z, rt.w };
        float bot[FF] = { dq0-kb[0], dq1-kb[1], dq2-kb[2], rb.x, rb.y, rb.z, rb.w };
        #pragma unroll
        for (int f = 0; f < FF; f++) {
            const float d = fmaf(top[f], ks[f], bot[f]*ks[7+f]);
            ftp[c][f] = __floats2half2_rn(d, d);
        }
    }
    __syncthreads();   // sWp visible

    const int i = bi & 1023;
    const size_t base = (((size_t)b*HH)*LL + i)*LL;

    for (int h = 0; h < HH; h += 4) {
        size_t ro[4];
        float sv[4][4];
        // all 4 S rows issued up-front (max load-level parallelism)
        #pragma unroll
        for (int hh = 0; hh < 4; hh++) {
            ro[hh] = base + (size_t)(h + hh) * LL * LL;
            const __half2 a = *(const __half2*)(S + ro[hh] + j0);
            const __half2 c = *(const __half2*)(S + ro[hh] + j0 + 2);
            sv[hh][0] = __low2float(a);  sv[hh][1] = __high2float(a);
            sv[hh][2] = __low2float(c);  sv[hh][3] = __high2float(c);
        }

        float vals[4][4];
        float sum[4];
        #pragma unroll
        for (int hh = 0; hh < 4; hh++) {
            __half2 w[FF];
            #pragma unroll
            for (int f = 0; f < FF; f++) w[f] = sWp[(h+hh)*FF + f];
            float lsum = 0.f;
            #pragma unroll
            for (int c = 0; c < 4; c++) {
                __half2 acc = __hmul2(ftp[c][0], w[0]);
                #pragma unroll
                for (int f = 1; f < FF; f++) acc = __hfma2(ftp[c][f], w[f], acc);
                const float dw = __low2float(acc);
                const float db = __high2float(acc);
                const float x2 = dw * dw;
                float sp = fmaf(x2, fmaf(x2, -(1.f/192.f), 0.125f),
                                fmaf(dw, 0.5f, 0.6931472f));
                if (fabsf(dw) > 1.0f)
                    sp = fmaxf(dw, 0.f) + __logf(1.f + __expf(-fabsf(dw)));
                vals[hh][c] = __expf(fmaf(sv[hh][c], sp, db));
                lsum += vals[hh][c];
            }
            sum[hh] = lsum;
        }

        // combined block reduction: four sums through one barrier pair
        #pragma unroll
        for (int o = 16; o; o >>= 1) {
            #pragma unroll
            for (int hh = 0; hh < 4; hh++)
                sum[hh] += __shfl_xor_sync(0xffffffffu, sum[hh], o);
        }
        __syncthreads();                 // red safe to overwrite
        if (lane == 0) {
            #pragma unroll
            for (int hh = 0; hh < 4; hh++) red[hh][wrp] = sum[hh];
        }
        __syncthreads();
        float tot[4];
        #pragma unroll
        for (int hh = 0; hh < 4; hh++) {
            float t = red[hh][0];
            #pragma unroll
            for (int k = 1; k < 8; k++) t += red[hh][k];
            tot[hh] = 1.f / t;
        }

        #pragma unroll
        for (int hh = 0; hh < 4; hh++) {
            const float a0 = vals[hh][0]*tot[hh], a1 = vals[hh][1]*tot[hh];
            const float a2 = vals[hh][2]*tot[hh], a3 = vals[hh][3]*tot[hh];
            *(float4*)(attn + ro[hh] + j0) = make_float4(a0, a1, a2, a3);
            __half2* AH = (__half2*)(attnH + ro[hh] + j0);
            AH[0] = __floats2half2_rn(a0, a1);
            AH[1] = __floats2half2_rn(a2, a3);
        }
    }
}

// ============================================================================
// launcher
// ============================================================================
extern "C" void kernel_launch(void* const* d_in, const int* in_sizes, int n_in,
                              void* d_out, int out_size)
{
    const float* q    = (const float*)d_in[0];
    const float* k    = (const float*)d_in[1];
    const float* v    = (const float*)d_in[2];
    const float* dq   = (const float*)d_in[3];
    const float* dkt  = (const float*)d_in[4];
    const float* dkb  = (const float*)d_in[5];
    const float* dks  = (const float*)d_in[6];
    const float* relt = (const float*)d_in[7];
    const float* relb = (const float*)d_in[8];
    const float* W_q  = (const float*)d_in[9];
    const float* b_q  = (const float*)d_in[10];
    const float* W_k  = (const float*)d_in[11];
    const float* W_v  = (const float*)d_in[12];
    // d_in[13] = W_c : unused by the outputs
    const float* W_w  = (const float*)d_in[14];
    const float* W_b  = (const float*)d_in[15];
    const float* W_o  = (const float*)d_in[16];
    const float* b_o  = (const float*)d_in[17];

    float* outO = (float*)d_out;               // [B,L,D]
    float* outA = outO + (size_t)BB*LL*DD;     // [B,H,L,L]

    __half *SH, *attnH, *xH, *WH, *QKVH, *AOH, *WoH;
    cudaGetSymbolAddress((void**)&SH,    g_SH);
    cudaGetSymbolAddress((void**)&attnH, g_attnH);
    cudaGetSymbolAddress((void**)&xH,    g_xH);
    cudaGetSymbolAddress((void**)&WH,    g_WH);
    cudaGetSymbolAddress((void**)&QKVH,  g_QKVH);
    cudaGetSymbolAddress((void**)&AOH,   g_AOH);
    cudaGetSymbolAddress((void**)&WoH,   g_WoH);

    __half* QH = QKVH;
    __half* KH = QKVH + (size_t)BLD;
    __half* VH = QKVH + (size_t)2*BLD;
    __half* Vt = xH;                           // xH free after projections

    const int SM_BIG = 3 * (128 + 256) * 144;   // 165888 (3-stage, K>=192)
    const int SM_AV  = 3 * (256 + 64)  * 144;   // 138240
    const int SM_SC  = 1 * (128 + 128) * 144;   // 36864 (1-stage, K=64)
    cudaFuncSetAttribute((const void*)hgemm<128,256,true>,
                         cudaFuncAttributeMaxDynamicSharedMemorySize, SM_BIG);
    cudaFuncSetAttribute((const void*)hgemm<128,256,false>,
                         cudaFuncAttributeMaxDynamicSharedMemorySize, SM_BIG);
    cudaFuncSetAttribute((const void*)hgemm<256,64,true>,
                         cudaFuncAttributeMaxDynamicSharedMemorySize, SM_AV);
    cudaFuncSetAttribute((const void*)hgemm<128,128,true>,
                         cudaFuncAttributeMaxDynamicSharedMemorySize, SM_SC);

    // ---- fused fp32 -> fp16 conversion of raw MMA operands ----
    {
        CvtArgs a;
        a.src[0] = q;   a.dst[0] = xH;           a.n8[0] = BLD/8;
        a.src[1] = k;   a.dst[1] = xH + BLD;     a.n8[1] = BLD/8;
        a.src[2] = v;   a.dst[2] = xH + 2*BLD;   a.n8[2] = BLD/8;
        a.src[3] = W_q; a.dst[3] = WH;           a.n8[3] = DD*DD/8;
        a.src[4] = W_k; a.dst[4] = WH + DD*DD;   a.n8[4] = DD*DD/8;
        a.src[5] = W_v; a.dst[5] = WH + 2*DD*DD; a.n8[5] = DD*DD/8;
        a.src[6] = W_o; a.dst[6] = WoH;          a.n8[6] = DD*DD/8;
        dim3 grid(148, 7, 1);
        cvt_f16<<<grid, 256>>>(a);
    }

    // ---- merged projections: {q,k,v} @ {Wq,Wk,Wv}^T, bias only for z=0 ----
    {
        dim3 grid(DD/256, (BB*LL)/128, 3);
        hgemm<128,256,true><<<grid, 256, SM_BIG>>>(xH, WH, b_q, QKVH,
            DD, DD, DD, DD, 1,
            (long long)BLD, 0, (long long)DD*DD, 0, (long long)BLD, 0, 1.f, 0);
    }

    // ---- scores: S[b,h] = (1/8) Qh @ Kh^T -> fp16. K=64 -> 1-stage smem,
    //      128-thread blocks, 2 blocks/SM for latency overlap ----
    {
        dim3 grid(LL/128, LL/128, BB*HH);
        hgemm<128,128,true><<<grid, 128, SM_SC>>>(QH, KH, nullptr, SH, DHH, DD, DD, LL,
            HH, (long long)LL*DD, 64, (long long)LL*DD, 64,
            (long long)HH*LL*LL, (long long)LL*LL, 0.125f, 0);
    }

    // ---- V per-head transpose into Vt ----
    {
        dim3 grid(LL/32, DHH/32, BB*HH);
        transposeV<<<grid, 256>>>(VH, Vt);
    }

    // ---- distmap bias + softmax -> attn fp32 (d_out) + fp16 (scratch) ----
    bias_softmax_kernel<<<BB*LL, 256>>>(
        SH, dq, dkt, dkb, dks, relt, relb, W_w, W_b, outA, attnH);

    // ---- attn @ Vh : M=1024, N=64, K=1024, batch 64, fp16 out ----
    {
        dim3 grid(1, LL/256, BB*HH);
        hgemm<256,64,true><<<grid, 128, SM_AV>>>(attnH, Vt, nullptr, AOH, LL, LL, LL, DD,
            HH, (long long)HH*LL*LL, (long long)LL*LL,
            (long long)HH*DHH*LL, (long long)DHH*LL,
            (long long)LL*DD, 64, 1.f, 0);
    }

    // ---- output projection: AO @ W_o^T + b_o (fp32 out) ----
    {
        dim3 grid(DD/256, (BB*LL)/128, 1);
        hgemm<128,256,false><<<grid, 256, SM_BIG>>>(AOH, WoH, b_o, outO, DD, DD, DD, DD,
                                                    1, 0,0,0,0,0,0, 1.f, 0);
    }
}

// round 14
// speedup vs baseline: 1.0165x; 1.0165x over previous
#include <cuda_runtime.h>
#include <cuda_fp16.h>
#include <cstdint>
#include <math.h>

#define BB  4
#define LL  1024
#define DD  1024
#define HH  16
#define DHH 64
#define FF  7
#define BLD (BB*LL*DD)

// ---- scratch (module-static device memory; no runtime allocation) ----
__device__ __align__(16) __half g_SH[(size_t)BB*HH*LL*LL];    // raw scores fp16
__device__ __align__(16) __half g_attnH[(size_t)BB*HH*LL*LL]; // attn fp16 copy
__device__ __align__(16) __half g_xH[3*BLD];      // fp16 q,k,v inputs; later Vt
__device__ __align__(16) __half g_WH[3*DD*DD];    // fp16 W_q,W_k,W_v
__device__ __align__(16) __half g_QKVH[3*BLD];    // projected Q,K,V fp16
__device__ __align__(16) __half g_AOH[BLD];
__device__ __align__(16) __half g_WoH[DD*DD];

// ============================================================================
// helpers
// ============================================================================
__device__ __forceinline__ uint32_t smem_u32(const void* p) {
    uint32_t a;
    asm("{ .reg .u64 t; cvta.to.shared.u64 t, %1; cvt.u32.u64 %0, t; }" : "=r"(a) : "l"(p));
    return a;
}
__device__ __forceinline__ void cp16(uint32_t s, const void* g) {
    asm volatile("cp.async.cg.shared.global [%0], [%1], 16;" :: "r"(s), "l"(g) : "memory");
}
#define CP_COMMIT() asm volatile("cp.async.commit_group;" ::: "memory")
#define CP_WAIT1()  asm volatile("cp.async.wait_group 1;" ::: "memory")

#define LDSM4(r0, r1, r2, r3, addr) \
    asm volatile("ldmatrix.sync.aligned.m8n8.x4.shared.b16 {%0,%1,%2,%3}, [%4];" \
        : "=r"(r0), "=r"(r1), "=r"(r2), "=r"(r3) : "r"(addr))

#define MMA_F16(c, a, b) \
    asm volatile("mma.sync.aligned.m16n8k16.row.col.f32.f16.f16.f32 " \
        "{%0,%1,%2,%3}, {%4,%5,%6,%7}, {%8,%9}, {%0,%1,%2,%3};" \
        : "+f"((c)[0]), "+f"((c)[1]), "+f"((c)[2]), "+f"((c)[3]) \
        : "r"((a)[0]), "r"((a)[1]), "r"((a)[2]), "r"((a)[3]), \
          "r"((b)[0]), "r"((b)[1]))

// ============================================================================
// fused fp32 -> fp16 conversion for 7 tensors (blockIdx.y selects tensor)
// ============================================================================
struct CvtArgs {
    const float* src[7];
    __half*      dst[7];
    int          n8[7];   // elements / 8
};

__global__ __launch_bounds__(256)
void cvt_f16(CvtArgs args)
{
    const int t = blockIdx.y;
    const float4* src = (const float4*)args.src[t];
    __half2*      dst = (__half2*)args.dst[t];
    const int n8 = args.n8[t];
    for (int i = blockIdx.x * 256 + threadIdx.x; i < n8; i += gridDim.x * 256) {
        float4 a = src[i * 2], b = src[i * 2 + 1];
        dst[i * 4 + 0] = __floats2half2_rn(a.x, a.y);
        dst[i * 4 + 1] = __floats2half2_rn(a.z, a.w);
        dst[i * 4 + 2] = __floats2half2_rn(b.x, b.y);
        dst[i * 4 + 3] = __floats2half2_rn(b.z, b.w);
    }
}

// ============================================================================
// Tensor-core fp16 GEMM (fp32 accum): C[m,n] = alpha*sum_k A[m,k]*B[n,k]
// (+bias[n] when zd==biasZ). 64x64 warp tiles; BK=64; up-to-3-stage cp.async.
// NOTE: launch with dynamic smem = min(K/64, 3) * (BM+BN) * 144 bytes.
// ============================================================================
template<int BM, int BN, bool HOUT>
__global__ void __launch_bounds__((BM/64)*(BN/64)*32)
hgemm(const __half* __restrict__ A, const __half* __restrict__ B,
      const float* __restrict__ bias, void* __restrict__ Cv,
      int K, int lda, int ldb, int ldc, int hmod,
      long long aS1, long long aS2, long long bS1, long long bS2,
      long long cS1, long long cS2, float alpha, int biasZ)
{
    constexpr int WARPS_M = BM / 64, WARPS_N = BN / 64;
    constexpr int NTHR = WARPS_M * WARPS_N * 32;
    constexpr int BK = 64;                 // halves per chunk
    constexpr int RB = 144;                // bytes per padded row
    constexpr int STB = (BM + BN) * RB;    // bytes per stage
    constexpr int A_IT = BM * 8 / NTHR;
    constexpr int B_IT = BN * 8 / NTHR;
    constexpr int RSTEP = NTHR / 8;
    constexpr int MT = 4, NT = 8;

    extern __shared__ char smc[];

    const int tid = threadIdx.x, lane = tid & 31, wid = tid >> 5;
    const int wm = wid % WARPS_M, wn = wid / WARPS_M;
    const int z = blockIdx.z, zd = z / hmod, zm = z % hmod;
    const __half* Ab = A + zd * aS1 + zm * aS2;
    const __half* Bb = B + zd * bS1 + zm * bS2;
    const int m0 = blockIdx.y * BM, n0 = blockIdx.x * BN;
    const bool useBias = (bias != nullptr) && (zd == biasZ);

    const int lrow = tid >> 3, lq = tid & 7;
    const __half* aG = Ab + (size_t)(m0 + lrow) * lda + lq * 8;
    const __half* bG = Bb + (size_t)(n0 + lrow) * ldb + lq * 8;
    const uint32_t smB = smem_u32(smc);
    const uint32_t aSo = (uint32_t)(lrow * RB + lq * 16);
    const uint32_t bSo = (uint32_t)((BM + lrow) * RB + lq * 16);

    const int mj = lane >> 3, mr = lane & 7;
    const int rowA  = wm * 64 + ((mj & 1) << 3) + mr;
    const uint32_t kByA = (uint32_t)(mj >> 1) * 16;
    const int rowB  = BM + wn * 64 + ((mj >> 1) << 3) + mr;
    const uint32_t kByB = (uint32_t)(mj & 1) * 16;

    float acc[MT][NT][4];
    #pragma unroll
    for (int i = 0; i < MT; i++)
        #pragma unroll
        for (int j = 0; j < NT; j++)
            #pragma unroll
            for (int r = 0; r < 4; r++) acc[i][j][r] = 0.f;

    const int NC = K / BK;

    auto LOAD = [&](int c, int s) {
        const uint32_t stb = smB + (uint32_t)s * STB;
        const __half* ap = aG + c * BK;
        const __half* bp = bG + c * BK;
        #pragma unroll
        for (int it = 0; it < A_IT; it++)
            cp16(stb + aSo + (uint32_t)it * RSTEP * RB,
                 ap + (size_t)it * RSTEP * lda);
        #pragma unroll
        for (int it = 0; it < B_IT; it++)
            cp16(stb + bSo + (uint32_t)it * RSTEP * RB,
                 bp + (size_t)it * RSTEP * ldb);
    };

    LOAD(0, 0); CP_COMMIT();
    if (NC > 1) LOAD(1, 1);
    CP_COMMIT();

    for (int c = 0; c < NC; c++) {
        CP_WAIT1();
        __syncthreads();
        if (c + 2 < NC) LOAD(c + 2, (c + 2) % 3);
        CP_COMMIT();

        const uint32_t stb = smB + (uint32_t)(c % 3) * STB;
        #pragma unroll
        for (int kk = 0; kk < 4; kk++) {
            uint32_t af[MT][4], bf[NT][2];
            #pragma unroll
            for (int mt = 0; mt < MT; mt++) {
                const uint32_t ad = stb + (uint32_t)(rowA + mt * 16) * RB
                                  + kk * 32 + kByA;
                LDSM4(af[mt][0], af[mt][1], af[mt][2], af[mt][3], ad);
            }
            #pragma unroll
            for (int p = 0; p < 4; p++) {
                const uint32_t bd = stb + (uint32_t)(rowB + p * 16) * RB
                                  + kk * 32 + kByB;
                LDSM4(bf[2*p][0], bf[2*p][1], bf[2*p+1][0], bf[2*p+1][1], bd);
            }
            #pragma unroll
            for (int mt = 0; mt < MT; mt++)
                #pragma unroll
                for (int nt = 0; nt < NT; nt++)
                    MMA_F16(acc[mt][nt], af[mt], bf[nt]);
        }
    }

    #pragma unroll
    for (int mt = 0; mt < MT; mt++) {
        const int m = m0 + wm * 64 + mt * 16 + (lane >> 2);
        #pragma unroll
        for (int nt = 0; nt < NT; nt++) {
            const int n = n0 + wn * 64 + nt * 8 + 2 * (lane & 3);
            float bx = 0.f, by = 0.f;
            if (useBias) { bx = bias[n]; by = bias[n + 1]; }
            float2 v0 = { acc[mt][nt][0] * alpha + bx, acc[mt][nt][1] * alpha + by };
            float2 v1 = { acc[mt][nt][2] * alpha + bx, acc[mt][nt][3] * alpha + by };
            if (HOUT) {
                __half* Cb = (__half*)Cv + zd * cS1 + zm * cS2;
                *(__half2*)(Cb + (size_t)m * ldc + n)       = __floats2half2_rn(v0.x, v0.y);
                *(__half2*)(Cb + (size_t)(m + 8) * ldc + n) = __floats2half2_rn(v1.x, v1.y);
            } else {
                float* Cb = (float*)Cv + zd * cS1 + zm * cS2;
                *(float2*)(Cb + (size_t)m * ldc + n)       = v0;
                *(float2*)(Cb + (size_t)(m + 8) * ldc + n) = v1;
            }
        }
    }
}

// ============================================================================
// per-head V transpose (fp16): Vt[(b*H+h)][n][k] = V[b][k][h*64+n]
// ============================================================================
__global__ __launch_bounds__(256)
void transposeV(const __half* __restrict__ V, __half* __restrict__ Vt)
{
    __shared__ __half t[32][34];
    const int z = blockIdx.z;
    const int b = z >> 4, h = z & 15;
    const int k0 = blockIdx.x * 32, n0 = blockIdx.y * 32;
    const int tx = threadIdx.x & 31, ty = threadIdx.x >> 5;
    #pragma unroll
    for (int i = 0; i < 4; i++)
        t[ty + 8 * i][tx] = V[((size_t)b * LL + k0 + ty + 8 * i) * DD + h * 64 + n0 + tx];
    __syncthreads();
    #pragma unroll
    for (int i = 0; i < 4; i++)
        Vt[((size_t)z * 64 + n0 + ty + 8 * i) * LL + k0 + tx] = t[tx][ty + 8 * i];
}

// ============================================================================
// Bias network + softmax v6 (R12 best): register features (half2), HFMA2
// dual dots, polynomial softplus, head-paired loop with combined reduction.
// ============================================================================
__global__ __launch_bounds__(256)
void bias_softmax_kernel(const __half* __restrict__ S,
                         const float* __restrict__ dq,
                         const float* __restrict__ dkt,
                         const float* __restrict__ dkb,
                         const float* __restrict__ dks,
                         const float* __restrict__ relt,
                         const float* __restrict__ relb,
                         const float* __restrict__ Ww,
                         const float* __restrict__ Wb,
                         float* __restrict__ attn,
                         __half* __restrict__ attnH)
{
    __shared__ __half2 sWp[HH*FF];   // (Ww, Wb) pairs
    __shared__ float red0[8], red1[8];

    const int bi  = blockIdx.x;
    const int b   = bi >> 10;
    const int tid = threadIdx.x;
    const int lane = tid & 31, wrp = tid >> 5;
    const int j0  = tid * 4;         // this thread owns columns j0..j0+3

    if (tid < HH*FF) sWp[tid] = __floats2half2_rn(Ww[tid], Wb[tid]);

    const float dq0 = dq[bi*3+0], dq1 = dq[bi*3+1], dq2 = dq[bi*3+2];
    const size_t riBase = (size_t)bi * LL * 4;

    // ---- features for 4 consecutive columns, packed (ft,ft) half2 ----
    __half2 ftp[4][FF];
    #pragma unroll
    for (int c = 0; c < 4; c++) {
        const int j = j0 + c;
        const float* kt = dkt + ((size_t)b*LL + j)*3;
        const float* kb = dkb + ((size_t)b*LL + j)*3;
        const float* ks = dks + ((size_t)b*LL + j)*14;
        const float4 rt = *(const float4*)(relt + riBase + (size_t)j*4);
        const float4 rb = *(const float4*)(relb + riBase + (size_t)j*4);
        float top[FF] = { dq0-kt[0], dq1-kt[1], dq2-kt[2], rt.x, rt.y, rt.z, rt.w };
        float bot[FF] = { dq0-kb[0], dq1-kb[1], dq2-kb[2], rb.x, rb.y, rb.z, rb.w };
        #pragma unroll
        for (int f = 0; f < FF; f++) {
            const float d = fmaf(top[f], ks[f], bot[f]*ks[7+f]);
            ftp[c][f] = __floats2half2_rn(d, d);
        }
    }
    __syncthreads();   // sWp visible

    const int i = bi & 1023;
    const size_t base = (((size_t)b*HH)*LL + i)*LL;

    for (int h = 0; h < HH; h += 2) {
        const size_t ro0 = base + (size_t)h * LL * LL;
        const size_t ro1 = ro0 + (size_t)LL * LL;
        // both S rows issued up-front (ILP across the pair)
        const __half2 sA0 = *(const __half2*)(S + ro0 + j0);
        const __half2 sB0 = *(const __half2*)(S + ro0 + j0 + 2);
        const __half2 sA1 = *(const __half2*)(S + ro1 + j0);
        const __half2 sB1 = *(const __half2*)(S + ro1 + j0 + 2);
        const float sv0[4] = { __low2float(sA0), __high2float(sA0),
                               __low2float(sB0), __high2float(sB0) };
        const float sv1[4] = { __low2float(sA1), __high2float(sA1),
                               __low2float(sB1), __high2float(sB1) };

        float vals0[4], vals1[4];
        float sum0 = 0.f, sum1 = 0.f;
        #pragma unroll
        for (int hh = 0; hh < 2; hh++) {
            __half2 w[FF];
            #pragma unroll
            for (int f = 0; f < FF; f++) w[f] = sWp[(h+hh)*FF + f];
            const float* sv = hh ? sv1 : sv0;
            float* vals = hh ? vals1 : vals0;
            float lsum = 0.f;
            #pragma unroll
            for (int c = 0; c < 4; c++) {
                __half2 acc = __hmul2(ftp[c][0], w[0]);
                #pragma unroll
                for (int f = 1; f < FF; f++) acc = __hfma2(ftp[c][f], w[f], acc);
                const float dw = __low2float(acc);
                const float db = __high2float(acc);
                const float x2 = dw * dw;
                float sp = fmaf(x2, fmaf(x2, -(1.f/192.f), 0.125f),
                                fmaf(dw, 0.5f, 0.6931472f));
                if (fabsf(dw) > 1.0f)
                    sp = fmaxf(dw, 0.f) + __logf(1.f + __expf(-fabsf(dw)));
                vals[c] = __expf(fmaf(sv[c], sp, db));
                lsum += vals[c];
            }
            if (hh) sum1 = lsum; else sum0 = lsum;
        }

        // combined block reduction: two sums through one barrier pair
        #pragma unroll
        for (int o = 16; o; o >>= 1) {
            sum0 += __shfl_xor_sync(0xffffffffu, sum0, o);
            sum1 += __shfl_xor_sync(0xffffffffu, sum1, o);
        }
        __syncthreads();                 // red safe to overwrite
        if (lane == 0) { red0[wrp] = sum0; red1[wrp] = sum1; }
        __syncthreads();
        float t0 = red0[0], t1 = red1[0];
        #pragma unroll
        for (int k = 1; k < 8; k++) { t0 += red0[k]; t1 += red1[k]; }
        const float inv0 = 1.f / t0, inv1 = 1.f / t1;

        float a0 = vals0[0]*inv0, a1 = vals0[1]*inv0,
              a2 = vals0[2]*inv0, a3 = vals0[3]*inv0;
        float b0 = vals1[0]*inv1, b1 = vals1[1]*inv1,
              b2 = vals1[2]*inv1, b3 = vals1[3]*inv1;

        *(float4*)(attn + ro0 + j0) = make_float4(a0, a1, a2, a3);
        *(float4*)(attn + ro1 + j0) = make_float4(b0, b1, b2, b3);
        __half2* A0 = (__half2*)(attnH + ro0 + j0);
        A0[0] = __floats2half2_rn(a0, a1);
        A0[1] = __floats2half2_rn(a2, a3);
        __half2* A1 = (__half2*)(attnH + ro1 + j0);
        A1[0] = __floats2half2_rn(b0, b1);
        A1[1] = __floats2half2_rn(b2, b3);
    }
}

// ============================================================================
// launcher
// ============================================================================
extern "C" void kernel_launch(void* const* d_in, const int* in_sizes, int n_in,
                              void* d_out, int out_size)
{
    const float* q    = (const float*)d_in[0];
    const float* k    = (const float*)d_in[1];
    const float* v    = (const float*)d_in[2];
    const float* dq   = (const float*)d_in[3];
    const float* dkt  = (const float*)d_in[4];
    const float* dkb  = (const float*)d_in[5];
    const float* dks  = (const float*)d_in[6];
    const float* relt = (const float*)d_in[7];
    const float* relb = (const float*)d_in[8];
    const float* W_q  = (const float*)d_in[9];
    const float* b_q  = (const float*)d_in[10];
    const float* W_k  = (const float*)d_in[11];
    const float* W_v  = (const float*)d_in[12];
    // d_in[13] = W_c : unused by the outputs
    const float* W_w  = (const float*)d_in[14];
    const float* W_b  = (const float*)d_in[15];
    const float* W_o  = (const float*)d_in[16];
    const float* b_o  = (const float*)d_in[17];

    float* outO = (float*)d_out;               // [B,L,D]
    float* outA = outO + (size_t)BB*LL*DD;     // [B,H,L,L]

    __half *SH, *attnH, *xH, *WH, *QKVH, *AOH, *WoH;
    cudaGetSymbolAddress((void**)&SH,    g_SH);
    cudaGetSymbolAddress((void**)&attnH, g_attnH);
    cudaGetSymbolAddress((void**)&xH,    g_xH);
    cudaGetSymbolAddress((void**)&WH,    g_WH);
    cudaGetSymbolAddress((void**)&QKVH,  g_QKVH);
    cudaGetSymbolAddress((void**)&AOH,   g_AOH);
    cudaGetSymbolAddress((void**)&WoH,   g_WoH);

    __half* QH = QKVH;
    __half* KH = QKVH + (size_t)BLD;
    __half* VH = QKVH + (size_t)2*BLD;
    __half* Vt = xH;                           // xH free after projections

    const int SM_MED = 3 * (128 + 128) * 144;   // 110592 (3-stage, 128x128)
    const int SM_AV  = 3 * (256 + 64)  * 144;   // 138240
    const int SM_SC  = 1 * (128 + 128) * 144;   // 36864 (1-stage, K=64)
    cudaFuncSetAttribute((const void*)hgemm<128,128,true>,
                         cudaFuncAttributeMaxDynamicSharedMemorySize, SM_MED);
    cudaFuncSetAttribute((const void*)hgemm<128,128,false>,
                         cudaFuncAttributeMaxDynamicSharedMemorySize, SM_MED);
    cudaFuncSetAttribute((const void*)hgemm<256,64,true>,
                         cudaFuncAttributeMaxDynamicSharedMemorySize, SM_AV);

    // ---- fused fp32 -> fp16 conversion of raw MMA operands ----
    {
        CvtArgs a;
        a.src[0] = q;   a.dst[0] = xH;           a.n8[0] = BLD/8;
        a.src[1] = k;   a.dst[1] = xH + BLD;     a.n8[1] = BLD/8;
        a.src[2] = v;   a.dst[2] = xH + 2*BLD;   a.n8[2] = BLD/8;
        a.src[3] = W_q; a.dst[3] = WH;           a.n8[3] = DD*DD/8;
        a.src[4] = W_k; a.dst[4] = WH + DD*DD;   a.n8[4] = DD*DD/8;
        a.src[5] = W_v; a.dst[5] = WH + 2*DD*DD; a.n8[5] = DD*DD/8;
        a.src[6] = W_o; a.dst[6] = WoH;          a.n8[6] = DD*DD/8;
        dim3 grid(148, 7, 1);
        cvt_f16<<<grid, 256>>>(a);
    }

    // ---- merged projections: {q,k,v} @ {Wq,Wk,Wv}^T, 128x128 tiles,
    //      128 threads, 3-stage -> 2 blocks/SM ----
    {
        dim3 grid(DD/128, (BB*LL)/128, 3);
        hgemm<128,128,true><<<grid, 128, SM_MED>>>(xH, WH, b_q, QKVH,
            DD, DD, DD, DD, 1,
            (long long)BLD, 0, (long long)DD*DD, 0, (long long)BLD, 0, 1.f, 0);
    }

    // ---- scores: S[b,h] = (1/8) Qh @ Kh^T -> fp16. K=64 -> 1-stage smem ----
    {
        dim3 grid(LL/128, LL/128, BB*HH);
        hgemm<128,128,true><<<grid, 128, SM_SC>>>(QH, KH, nullptr, SH, DHH, DD, DD, LL,
            HH, (long long)LL*DD, 64, (long long)LL*DD, 64,
            (long long)HH*LL*LL, (long long)LL*LL, 0.125f, 0);
    }

    // ---- V per-head transpose into Vt ----
    {
        dim3 grid(LL/32, DHH/32, BB*HH);
        transposeV<<<grid, 256>>>(VH, Vt);
    }

    // ---- distmap bias + softmax -> attn fp32 (d_out) + fp16 (scratch) ----
    bias_softmax_kernel<<<BB*LL, 256>>>(
        SH, dq, dkt, dkb, dks, relt, relb, W_w, W_b, outA, attnH);

    // ---- attn @ Vh : M=1024, N=64, K=1024, batch 64, fp16 out ----
    {
        dim3 grid(1, LL/256, BB*HH);
        hgemm<256,64,true><<<grid, 128, SM_AV>>>(attnH, Vt, nullptr, AOH, LL, LL, LL, DD,
            HH, (long long)HH*LL*LL, (long long)LL*LL,
            (long long)HH*DHH*LL, (long long)DHH*LL,
            (long long)LL*DD, 64, 1.f, 0);
    }

    // ---- output projection: AO @ W_o^T + b_o (fp32 out), 128x128 tiles ----
    {
        dim3 grid(DD/128, (BB*LL)/128, 1);
        hgemm<128,128,false><<<grid, 128, SM_MED>>>(AOH, WoH, b_o, outO, DD, DD, DD, DD,
                                                    1, 0,0,0,0,0,0, 1.f, 0);
    }
}

// round 15
// speedup vs baseline: 1.0264x; 1.0097x over previous
#include <cuda_runtime.h>
#include <cuda_fp16.h>
#include <cstdint>
#include <math.h>

#define BB  4
#define LL  1024
#define DD  1024
#define HH  16
#define DHH 64
#define FF  7
#define BLD (BB*LL*DD)

// ---- scratch (module-static device memory; no runtime allocation) ----
__device__ __align__(16) __half g_SH[(size_t)BB*HH*LL*LL];    // raw scores fp16
__device__ __align__(16) __half g_attnH[(size_t)BB*HH*LL*LL]; // attn fp16 copy
__device__ __align__(16) __half g_xH[3*BLD];      // fp16 q,k,v inputs; later Vt
__device__ __align__(16) __half g_WH[3*DD*DD];    // fp16 W_q,W_k,W_v
__device__ __align__(16) __half g_QKVH[3*BLD];    // projected Q,K,V fp16
__device__ __align__(16) __half g_AOH[BLD];
__device__ __align__(16) __half g_WoH[DD*DD];

// ============================================================================
// helpers
// ============================================================================
__device__ __forceinline__ uint32_t smem_u32(const void* p) {
    uint32_t a;
    asm("{ .reg .u64 t; cvta.to.shared.u64 t, %1; cvt.u32.u64 %0, t; }" : "=r"(a) : "l"(p));
    return a;
}
__device__ __forceinline__ void cp16(uint32_t s, const void* g) {
    asm volatile("cp.async.cg.shared.global [%0], [%1], 16;" :: "r"(s), "l"(g) : "memory");
}
#define CP_COMMIT() asm volatile("cp.async.commit_group;" ::: "memory")
#define CP_WAIT1()  asm volatile("cp.async.wait_group 1;" ::: "memory")

#define LDSM4(r0, r1, r2, r3, addr) \
    asm volatile("ldmatrix.sync.aligned.m8n8.x4.shared.b16 {%0,%1,%2,%3}, [%4];" \
        : "=r"(r0), "=r"(r1), "=r"(r2), "=r"(r3) : "r"(addr))

#define MMA_F16(c, a, b) \
    asm volatile("mma.sync.aligned.m16n8k16.row.col.f32.f16.f16.f32 " \
        "{%0,%1,%2,%3}, {%4,%5,%6,%7}, {%8,%9}, {%0,%1,%2,%3};" \
        : "+f"((c)[0]), "+f"((c)[1]), "+f"((c)[2]), "+f"((c)[3]) \
        : "r"((a)[0]), "r"((a)[1]), "r"((a)[2]), "r"((a)[3]), \
          "r"((b)[0]), "r"((b)[1]))

// ---- streaming (evict-first) load/store hints ----
__device__ __forceinline__ uint32_t ldcs_u32(const void* p) {
    uint32_t v;
    asm volatile("ld.global.cs.b32 %0, [%1];" : "=r"(v) : "l"(p));
    return v;
}
__device__ __forceinline__ float4 ldcs_f4(const void* p) {
    float4 v;
    asm volatile("ld.global.cs.v4.f32 {%0,%1,%2,%3}, [%4];"
                 : "=f"(v.x), "=f"(v.y), "=f"(v.z), "=f"(v.w) : "l"(p));
    return v;
}
__device__ __forceinline__ void stcs_f4(void* p, float4 v) {
    asm volatile("st.global.cs.v4.f32 [%0], {%1,%2,%3,%4};"
                 :: "l"(p), "f"(v.x), "f"(v.y), "f"(v.z), "f"(v.w) : "memory");
}
__device__ __forceinline__ void stcs_f2(void* p, float2 v) {
    asm volatile("st.global.cs.v2.f32 [%0], {%1,%2};"
                 :: "l"(p), "f"(v.x), "f"(v.y) : "memory");
}
__device__ __forceinline__ void stcs_u32(void* p, uint32_t v) {
    asm volatile("st.global.cs.b32 [%0], %1;" :: "l"(p), "r"(v) : "memory");
}
__device__ __forceinline__ uint32_t h2_bits(__half2 h) {
    union { __half2 h; uint32_t u; } c; c.h = h; return c.u;
}
__device__ __forceinline__ __half2 bits_h2(uint32_t u) {
    union { __half2 h; uint32_t u; } c; c.u = u; return c.h;
}

// ============================================================================
// fused fp32 -> fp16 conversion for 7 tensors (blockIdx.y selects tensor)
// ============================================================================
struct CvtArgs {
    const float* src[7];
    __half*      dst[7];
    int          n8[7];   // elements / 8
};

__global__ __launch_bounds__(256)
void cvt_f16(CvtArgs args)
{
    const int t = blockIdx.y;
    const float4* src = (const float4*)args.src[t];
    __half2*      dst = (__half2*)args.dst[t];
    const int n8 = args.n8[t];
    for (int i = blockIdx.x * 256 + threadIdx.x; i < n8; i += gridDim.x * 256) {
        float4 a = src[i * 2], b = src[i * 2 + 1];
        dst[i * 4 + 0] = __floats2half2_rn(a.x, a.y);
        dst[i * 4 + 1] = __floats2half2_rn(a.z, a.w);
        dst[i * 4 + 2] = __floats2half2_rn(b.x, b.y);
        dst[i * 4 + 3] = __floats2half2_rn(b.z, b.w);
    }
}

// ============================================================================
// Tensor-core fp16 GEMM (fp32 accum): C[m,n] = alpha*sum_k A[m,k]*B[n,k]
// (+bias[n] when zd==biasZ). 64x64 warp tiles; BK=64; up-to-3-stage cp.async.
// STRM: evict-first C stores (for single-use / final outputs).
// ============================================================================
template<int BM, int BN, bool HOUT, bool STRM>
__global__ void __launch_bounds__((BM/64)*(BN/64)*32)
hgemm(const __half* __restrict__ A, const __half* __restrict__ B,
      const float* __restrict__ bias, void* __restrict__ Cv,
      int K, int lda, int ldb, int ldc, int hmod,
      long long aS1, long long aS2, long long bS1, long long bS2,
      long long cS1, long long cS2, float alpha, int biasZ)
{
    constexpr int WARPS_M = BM / 64, WARPS_N = BN / 64;
    constexpr int NTHR = WARPS_M * WARPS_N * 32;
    constexpr int BK = 64;                 // halves per chunk
    constexpr int RB = 144;                // bytes per padded row
    constexpr int STB = (BM + BN) * RB;    // bytes per stage
    constexpr int A_IT = BM * 8 / NTHR;
    constexpr int B_IT = BN * 8 / NTHR;
    constexpr int RSTEP = NTHR / 8;
    constexpr int MT = 4, NT = 8;

    extern __shared__ char smc[];

    const int tid = threadIdx.x, lane = tid & 31, wid = tid >> 5;
    const int wm = wid % WARPS_M, wn = wid / WARPS_M;
    const int z = blockIdx.z, zd = z / hmod, zm = z % hmod;
    const __half* Ab = A + zd * aS1 + zm * aS2;
    const __half* Bb = B + zd * bS1 + zm * bS2;
    const int m0 = blockIdx.y * BM, n0 = blockIdx.x * BN;
    const bool useBias = (bias != nullptr) && (zd == biasZ);

    const int lrow = tid >> 3, lq = tid & 7;
    const __half* aG = Ab + (size_t)(m0 + lrow) * lda + lq * 8;
    const __half* bG = Bb + (size_t)(n0 + lrow) * ldb + lq * 8;
    const uint32_t smB = smem_u32(smc);
    const uint32_t aSo = (uint32_t)(lrow * RB + lq * 16);
    const uint32_t bSo = (uint32_t)((BM + lrow) * RB + lq * 16);

    const int mj = lane >> 3, mr = lane & 7;
    const int rowA  = wm * 64 + ((mj & 1) << 3) + mr;
    const uint32_t kByA = (uint32_t)(mj >> 1) * 16;
    const int rowB  = BM + wn * 64 + ((mj >> 1) << 3) + mr;
    const uint32_t kByB = (uint32_t)(mj & 1) * 16;

    float acc[MT][NT][4];
    #pragma unroll
    for (int i = 0; i < MT; i++)
        #pragma unroll
        for (int j = 0; j < NT; j++)
            #pragma unroll
            for (int r = 0; r < 4; r++) acc[i][j][r] = 0.f;

    const int NC = K / BK;

    auto LOAD = [&](int c, int s) {
        const uint32_t stb = smB + (uint32_t)s * STB;
        const __half* ap = aG + c * BK;
        const __half* bp = bG + c * BK;
        #pragma unroll
        for (int it = 0; it < A_IT; it++)
            cp16(stb + aSo + (uint32_t)it * RSTEP * RB,
                 ap + (size_t)it * RSTEP * lda);
        #pragma unroll
        for (int it = 0; it < B_IT; it++)
            cp16(stb + bSo + (uint32_t)it * RSTEP * RB,
                 bp + (size_t)it * RSTEP * ldb);
    };

    LOAD(0, 0); CP_COMMIT();
    if (NC > 1) LOAD(1, 1);
    CP_COMMIT();

    for (int c = 0; c < NC; c++) {
        CP_WAIT1();
        __syncthreads();
        if (c + 2 < NC) LOAD(c + 2, (c + 2) % 3);
        CP_COMMIT();

        const uint32_t stb = smB + (uint32_t)(c % 3) * STB;
        #pragma unroll
        for (int kk = 0; kk < 4; kk++) {
            uint32_t af[MT][4], bf[NT][2];
            #pragma unroll
            for (int mt = 0; mt < MT; mt++) {
                const uint32_t ad = stb + (uint32_t)(rowA + mt * 16) * RB
                                  + kk * 32 + kByA;
                LDSM4(af[mt][0], af[mt][1], af[mt][2], af[mt][3], ad);
            }
            #pragma unroll
            for (int p = 0; p < 4; p++) {
                const uint32_t bd = stb + (uint32_t)(rowB + p * 16) * RB
                                  + kk * 32 + kByB;
                LDSM4(bf[2*p][0], bf[2*p][1], bf[2*p+1][0], bf[2*p+1][1], bd);
            }
            #pragma unroll
            for (int mt = 0; mt < MT; mt++)
                #pragma unroll
                for (int nt = 0; nt < NT; nt++)
                    MMA_F16(acc[mt][nt], af[mt], bf[nt]);
        }
    }

    #pragma unroll
    for (int mt = 0; mt < MT; mt++) {
        const int m = m0 + wm * 64 + mt * 16 + (lane >> 2);
        #pragma unroll
        for (int nt = 0; nt < NT; nt++) {
            const int n = n0 + wn * 64 + nt * 8 + 2 * (lane & 3);
            float bx = 0.f, by = 0.f;
            if (useBias) { bx = bias[n]; by = bias[n + 1]; }
            float2 v0 = { acc[mt][nt][0] * alpha + bx, acc[mt][nt][1] * alpha + by };
            float2 v1 = { acc[mt][nt][2] * alpha + bx, acc[mt][nt][3] * alpha + by };
            if (HOUT) {
                __half* Cb = (__half*)Cv + zd * cS1 + zm * cS2;
                const uint32_t h0 = h2_bits(__floats2half2_rn(v0.x, v0.y));
                const uint32_t h1 = h2_bits(__floats2half2_rn(v1.x, v1.y));
                if (STRM) {
                    stcs_u32(Cb + (size_t)m * ldc + n, h0);
                    stcs_u32(Cb + (size_t)(m + 8) * ldc + n, h1);
                } else {
                    *(uint32_t*)(Cb + (size_t)m * ldc + n)       = h0;
                    *(uint32_t*)(Cb + (size_t)(m + 8) * ldc + n) = h1;
                }
            } else {
                float* Cb = (float*)Cv + zd * cS1 + zm * cS2;
                if (STRM) {
                    stcs_f2(Cb + (size_t)m * ldc + n, v0);
                    stcs_f2(Cb + (size_t)(m + 8) * ldc + n, v1);
                } else {
                    *(float2*)(Cb + (size_t)m * ldc + n)       = v0;
                    *(float2*)(Cb + (size_t)(m + 8) * ldc + n) = v1;
                }
            }
        }
    }
}

// ============================================================================
// per-head V transpose (fp16): Vt[(b*H+h)][n][k] = V[b][k][h*64+n]
// ============================================================================
__global__ __launch_bounds__(256)
void transposeV(const __half* __restrict__ V, __half* __restrict__ Vt)
{
    __shared__ __half t[32][34];
    const int z = blockIdx.z;
    const int b = z >> 4, h = z & 15;
    const int k0 = blockIdx.x * 32, n0 = blockIdx.y * 32;
    const int tx = threadIdx.x & 31, ty = threadIdx.x >> 5;
    #pragma unroll
    for (int i = 0; i < 4; i++)
        t[ty + 8 * i][tx] = V[((size_t)b * LL + k0 + ty + 8 * i) * DD + h * 64 + n0 + tx];
    __syncthreads();
    #pragma unroll
    for (int i = 0; i < 4; i++)
        Vt[((size_t)z * 64 + n0 + ty + 8 * i) * LL + k0 + tx] = t[tx][ty + 8 * i];
}

// ============================================================================
// Bias network + softmax (R12 structure + streaming cache hints):
// register features (half2), HFMA2 dual dots, polynomial softplus,
// head-paired loop; S/rel via ld.cs, attn fp32 via st.cs.
// ============================================================================
__global__ __launch_bounds__(256)
void bias_softmax_kernel(const __half* __restrict__ S,
                         const float* __restrict__ dq,
                         const float* __restrict__ dkt,
                         const float* __restrict__ dkb,
                         const float* __restrict__ dks,
                         const float* __restrict__ relt,
                         const float* __restrict__ relb,
                         const float* __restrict__ Ww,
                         const float* __restrict__ Wb,
                         float* __restrict__ attn,
                         __half* __restrict__ attnH)
{
    __shared__ __half2 sWp[HH*FF];   // (Ww, Wb) pairs
    __shared__ float red0[8], red1[8];

    const int bi  = blockIdx.x;
    const int b   = bi >> 10;
    const int tid = threadIdx.x;
    const int lane = tid & 31, wrp = tid >> 5;
    const int j0  = tid * 4;         // this thread owns columns j0..j0+3

    if (tid < HH*FF) sWp[tid] = __floats2half2_rn(Ww[tid], Wb[tid]);

    const float dq0 = dq[bi*3+0], dq1 = dq[bi*3+1], dq2 = dq[bi*3+2];
    const size_t riBase = (size_t)bi * LL * 4;

    // ---- features for 4 consecutive columns, packed (ft,ft) half2 ----
    __half2 ftp[4][FF];
    #pragma unroll
    for (int c = 0; c < 4; c++) {
        const int j = j0 + c;
        const float* kt = dkt + ((size_t)b*LL + j)*3;
        const float* kb = dkb + ((size_t)b*LL + j)*3;
        const float* ks = dks + ((size_t)b*LL + j)*14;
        const float4 rt = ldcs_f4(relt + riBase + (size_t)j*4);
        const float4 rb = ldcs_f4(relb + riBase + (size_t)j*4);
        float top[FF] = { dq0-kt[0], dq1-kt[1], dq2-kt[2], rt.x, rt.y, rt.z, rt.w };
        float bot[FF] = { dq0-kb[0], dq1-kb[1], dq2-kb[2], rb.x, rb.y, rb.z, rb.w };
        #pragma unroll
        for (int f = 0; f < FF; f++) {
            const float d = fmaf(top[f], ks[f], bot[f]*ks[7+f]);
            ftp[c][f] = __floats2half2_rn(d, d);
        }
    }
    __syncthreads();   // sWp visible

    const int i = bi & 1023;
    const size_t base = (((size_t)b*HH)*LL + i)*LL;

    for (int h = 0; h < HH; h += 2) {
        const size_t ro0 = base + (size_t)h * LL * LL;
        const size_t ro1 = ro0 + (size_t)LL * LL;
        // both S rows issued up-front (ILP across the pair), evict-first
        const __half2 sA0 = bits_h2(ldcs_u32(S + ro0 + j0));
        const __half2 sB0 = bits_h2(ldcs_u32(S + ro0 + j0 + 2));
        const __half2 sA1 = bits_h2(ldcs_u32(S + ro1 + j0));
        const __half2 sB1 = bits_h2(ldcs_u32(S + ro1 + j0 + 2));
        const float sv0[4] = { __low2float(sA0), __high2float(sA0),
                               __low2float(sB0), __high2float(sB0) };
        const float sv1[4] = { __low2float(sA1), __high2float(sA1),
                               __low2float(sB1), __high2float(sB1) };

        float vals0[4], vals1[4];
        float sum0 = 0.f, sum1 = 0.f;
        #pragma unroll
        for (int hh = 0; hh < 2; hh++) {
            __half2 w[FF];
            #pragma unroll
            for (int f = 0; f < FF; f++) w[f] = sWp[(h+hh)*FF + f];
            const float* sv = hh ? sv1 : sv0;
            float* vals = hh ? vals1 : vals0;
            float lsum = 0.f;
            #pragma unroll
            for (int c = 0; c < 4; c++) {
                __half2 acc = __hmul2(ftp[c][0], w[0]);
                #pragma unroll
                for (int f = 1; f < FF; f++) acc = __hfma2(ftp[c][f], w[f], acc);
                const float dw = __low2float(acc);
                const float db = __high2float(acc);
                const float x2 = dw * dw;
                float sp = fmaf(x2, fmaf(x2, -(1.f/192.f), 0.125f),
                                fmaf(dw, 0.5f, 0.6931472f));
                if (fabsf(dw) > 1.0f)
                    sp = fmaxf(dw, 0.f) + __logf(1.f + __expf(-fabsf(dw)));
                vals[c] = __expf(fmaf(sv[c], sp, db));
                lsum += vals[c];
            }
            if (hh) sum1 = lsum; else sum0 = lsum;
        }

        // combined block reduction: two sums through one barrier pair
        #pragma unroll
        for (int o = 16; o; o >>= 1) {
            sum0 += __shfl_xor_sync(0xffffffffu, sum0, o);
            sum1 += __shfl_xor_sync(0xffffffffu, sum1, o);
        }
        __syncthreads();                 // red safe to overwrite
        if (lane == 0) { red0[wrp] = sum0; red1[wrp] = sum1; }
        __syncthreads();
        float t0 = red0[0], t1 = red1[0];
        #pragma unroll
        for (int k = 1; k < 8; k++) { t0 += red0[k]; t1 += red1[k]; }
        const float inv0 = 1.f / t0, inv1 = 1.f / t1;

        float a0 = vals0[0]*inv0, a1 = vals0[1]*inv0,
              a2 = vals0[2]*inv0, a3 = vals0[3]*inv0;
        float b0 = vals1[0]*inv1, b1 = vals1[1]*inv1,
              b2 = vals1[2]*inv1, b3 = vals1[3]*inv1;

        // fp32 attn: final output, never re-read -> evict-first
        stcs_f4(attn + ro0 + j0, make_float4(a0, a1, a2, a3));
        stcs_f4(attn + ro1 + j0, make_float4(b0, b1, b2, b3));
        // fp16 copy: consumed by attn@V soon -> default policy
        __half2* A0 = (__half2*)(attnH + ro0 + j0);
        A0[0] = __floats2half2_rn(a0, a1);
        A0[1] = __floats2half2_rn(a2, a3);
        __half2* A1 = (__half2*)(attnH + ro1 + j0);
        A1[0] = __floats2half2_rn(b0, b1);
        A1[1] = __floats2half2_rn(b2, b3);
    }
}

// ============================================================================
// launcher
// ============================================================================
extern "C" void kernel_launch(void* const* d_in, const int* in_sizes, int n_in,
                              void* d_out, int out_size)
{
    const float* q    = (const float*)d_in[0];
    const float* k    = (const float*)d_in[1];
    const float* v    = (const float*)d_in[2];
    const float* dq   = (const float*)d_in[3];
    const float* dkt  = (const float*)d_in[4];
    const float* dkb  = (const float*)d_in[5];
    const float* dks  = (const float*)d_in[6];
    const float* relt = (const float*)d_in[7];
    const float* relb = (const float*)d_in[8];
    const float* W_q  = (const float*)d_in[9];
    const float* b_q  = (const float*)d_in[10];
    const float* W_k  = (const float*)d_in[11];
    const float* W_v  = (const float*)d_in[12];
    // d_in[13] = W_c : unused by the outputs
    const float* W_w  = (const float*)d_in[14];
    const float* W_b  = (const float*)d_in[15];
    const float* W_o  = (const float*)d_in[16];
    const float* b_o  = (const float*)d_in[17];

    float* outO = (float*)d_out;               // [B,L,D]
    float* outA = outO + (size_t)BB*LL*DD;     // [B,H,L,L]

    __half *SH, *attnH, *xH, *WH, *QKVH, *AOH, *WoH;
    cudaGetSymbolAddress((void**)&SH,    g_SH);
    cudaGetSymbolAddress((void**)&attnH, g_attnH);
    cudaGetSymbolAddress((void**)&xH,    g_xH);
    cudaGetSymbolAddress((void**)&WH,    g_WH);
    cudaGetSymbolAddress((void**)&QKVH,  g_QKVH);
    cudaGetSymbolAddress((void**)&AOH,   g_AOH);
    cudaGetSymbolAddress((void**)&WoH,   g_WoH);

    __half* QH = QKVH;
    __half* KH = QKVH + (size_t)BLD;
    __half* VH = QKVH + (size_t)2*BLD;
    __half* Vt = xH;                           // xH free after projections

    const int SM_MED = 3 * (128 + 128) * 144;   // 110592 (3-stage, 128x128)
    const int SM_AV  = 3 * (256 + 64)  * 144;   // 138240
    const int SM_SC  = 1 * (128 + 128) * 144;   // 36864 (1-stage, K=64)
    cudaFuncSetAttribute((const void*)hgemm<128,128,true,false>,
                         cudaFuncAttributeMaxDynamicSharedMemorySize, SM_MED);
    cudaFuncSetAttribute((const void*)hgemm<128,128,true,true>,
                         cudaFuncAttributeMaxDynamicSharedMemorySize, SM_SC);
    cudaFuncSetAttribute((const void*)hgemm<128,128,false,true>,
                         cudaFuncAttributeMaxDynamicSharedMemorySize, SM_MED);
    cudaFuncSetAttribute((const void*)hgemm<256,64,true,false>,
                         cudaFuncAttributeMaxDynamicSharedMemorySize, SM_AV);

    // ---- fused fp32 -> fp16 conversion of raw MMA operands ----
    {
        CvtArgs a;
        a.src[0] = q;   a.dst[0] = xH;           a.n8[0] = BLD/8;
        a.src[1] = k;   a.dst[1] = xH + BLD;     a.n8[1] = BLD/8;
        a.src[2] = v;   a.dst[2] = xH + 2*BLD;   a.n8[2] = BLD/8;
        a.src[3] = W_q; a.dst[3] = WH;           a.n8[3] = DD*DD/8;
        a.src[4] = W_k; a.dst[4] = WH + DD*DD;   a.n8[4] = DD*DD/8;
        a.src[5] = W_v; a.dst[5] = WH + 2*DD*DD; a.n8[5] = DD*DD/8;
        a.src[6] = W_o; a.dst[6] = WoH;          a.n8[6] = DD*DD/8;
        dim3 grid(148, 7, 1);
        cvt_f16<<<grid, 256>>>(a);
    }

    // ---- merged projections: {q,k,v} @ {Wq,Wk,Wv}^T, 128x128 tiles ----
    {
        dim3 grid(DD/128, (BB*LL)/128, 3);
        hgemm<128,128,true,false><<<grid, 128, SM_MED>>>(xH, WH, b_q, QKVH,
            DD, DD, DD, DD, 1,
            (long long)BLD, 0, (long long)DD*DD, 0, (long long)BLD, 0, 1.f, 0);
    }

    // ---- scores: S[b,h] = (1/8) Qh @ Kh^T -> fp16, streaming C stores ----
    {
        dim3 grid(LL/128, LL/128, BB*HH);
        hgemm<128,128,true,true><<<grid, 128, SM_SC>>>(QH, KH, nullptr, SH, DHH, DD, DD, LL,
            HH, (long long)LL*DD, 64, (long long)LL*DD, 64,
            (long long)HH*LL*LL, (long long)LL*LL, 0.125f, 0);
    }

    // ---- V per-head transpose into Vt ----
    {
        dim3 grid(LL/32, DHH/32, BB*HH);
        transposeV<<<grid, 256>>>(VH, Vt);
    }

    // ---- distmap bias + softmax -> attn fp32 (d_out, st.cs) + fp16 ----
    bias_softmax_kernel<<<BB*LL, 256>>>(
        SH, dq, dkt, dkb, dks, relt, relb, W_w, W_b, outA, attnH);

    // ---- attn @ Vh : M=1024, N=64, K=1024, batch 64, fp16 out ----
    {
        dim3 grid(1, LL/256, BB*HH);
        hgemm<256,64,true,false><<<grid, 128, SM_AV>>>(attnH, Vt, nullptr, AOH, LL, LL, LL, DD,
            HH, (long long)HH*LL*LL, (long long)LL*LL,
            (long long)HH*DHH*LL, (long long)DHH*LL,
            (long long)LL*DD, 64, 1.f, 0);
    }

    // ---- output projection: AO @ W_o^T + b_o (fp32 out, streaming) ----
    {
        dim3 grid(DD/128, (BB*LL)/128, 1);
        hgemm<128,128,false,true><<<grid, 128, SM_MED>>>(AOH, WoH, b_o, outO, DD, DD, DD, DD,
                                                         1, 0,0,0,0,0,0, 1.f, 0);
    }
}